// round 1
// baseline (speedup 1.0000x reference)
#include <cuda_runtime.h>
#include <cstddef>

#define NLAYER 8
#define DMODEL 2048
#define NHEAD 8
#define NKV 2
#define HDIM 256
#define SEQ 4096
#define FFDIM 8192
#define PLDIM 256
#define POS 2048
#define NS 2049          // valid attention positions (0..POS)
#define SSTR 2080        // padded score row stride
#define EPSF 1e-6f

// ---------------- scratch (device global, no allocation) ----------------
// layout (floats):
//  h: 0            (2048)
//  hn: 2048        (2048)
//  qkv: 4096       (3072)
//  q: 7168         (2048)
//  knew: 9216      (512)
//  vnew: 9728      (512)
//  attn: 10240     (2048)
//  act: 12288      (8192)
//  vec: 20480      (2048)   (generic gemv output: attn2raw/mlpraw/plraw)
//  g2: 22528       (256)
//  scores: 22784   (8*2080 = 16640)
#define OFF_H     0
#define OFF_HN    2048
#define OFF_QKV   4096
#define OFF_Q     7168
#define OFF_KNEW  9216
#define OFF_VNEW  9728
#define OFF_ATTN  10240
#define OFF_ACT   12288
#define OFF_VEC   20480
#define OFF_G2    22528
#define OFF_SC    22784
__device__ __align__(16) float g_scratch[22784 + 8 * SSTR];

// ---------------- helpers ----------------
__device__ __forceinline__ float warp_sum(float v) {
#pragma unroll
    for (int o = 16; o; o >>= 1) v += __shfl_xor_sync(0xffffffffu, v, o);
    return v;
}
__device__ __forceinline__ float warp_max(float v) {
#pragma unroll
    for (int o = 16; o; o >>= 1) v = fmaxf(v, __shfl_xor_sync(0xffffffffu, v, o));
    return v;
}
__device__ __forceinline__ float block_sum(float v) {
    __shared__ float red[16];
    __shared__ float tot;
    int t = threadIdx.x, nw = (int)(blockDim.x >> 5);
    __syncthreads();
    v = warp_sum(v);
    if ((t & 31) == 0) red[t >> 5] = v;
    __syncthreads();
    if (t < 32) {
        float s = (t < nw) ? red[t] : 0.f;
        s = warp_sum(s);
        if (t == 0) tot = s;
    }
    __syncthreads();
    return tot;
}
__device__ __forceinline__ float block_max(float v) {
    __shared__ float red[16];
    __shared__ float tot;
    int t = threadIdx.x, nw = (int)(blockDim.x >> 5);
    __syncthreads();
    v = warp_max(v);
    if ((t & 31) == 0) red[t >> 5] = v;
    __syncthreads();
    if (t < 32) {
        float s = (t < nw) ? red[t] : -3.0e38f;
        s = warp_max(s);
        if (t == 0) tot = s;
    }
    __syncthreads();
    return tot;
}
__device__ __forceinline__ float gelu_t(float x) {
    float x3 = x * x * x;
    return 0.5f * x * (1.f + tanhf(0.7978845608028654f * (x + 0.044715f * x3)));
}

// ---------------- kernels ----------------

// big KV copy: K_in,V_in -> out (float4 grid-stride)
__global__ void k_copy_kv(const float4* __restrict__ a, const float4* __restrict__ b,
                          float4* __restrict__ oa, float4* __restrict__ ob, int n4) {
    int i = blockIdx.x * blockDim.x + threadIdx.x;
    int stride = gridDim.x * blockDim.x;
    for (; i < n4; i += stride) {
        oa[i] = a[i];
        ob[i] = b[i];
    }
}

__global__ void k_copy(const float* __restrict__ src, float* __restrict__ dst, int n) {
    int i = blockIdx.x * blockDim.x + threadIdx.x;
    if (i < n) dst[i] = src[i];
}

// out = rms(x)*w   (1 block, 512 threads, D=2048)
__global__ void k_rms_scale(const float* __restrict__ x, const float* __restrict__ w,
                            float* __restrict__ out) {
    int t = threadIdx.x;
    float v[4];
    float ss = 0.f;
#pragma unroll
    for (int i = 0; i < 4; i++) { v[i] = x[t + 512 * i]; ss += v[i] * v[i]; }
    ss = block_sum(ss);
    float inv = rsqrtf(ss / (float)DMODEL + EPSF);
#pragma unroll
    for (int i = 0; i < 4; i++) out[t + 512 * i] = v[i] * inv * w[t + 512 * i];
}

// h += rms(raw)*w
__global__ void k_rms_add(const float* __restrict__ raw, const float* __restrict__ w,
                          float* __restrict__ h) {
    int t = threadIdx.x;
    float v[4];
    float ss = 0.f;
#pragma unroll
    for (int i = 0; i < 4; i++) { v[i] = raw[t + 512 * i]; ss += v[i] * v[i]; }
    ss = block_sum(ss);
    float inv = rsqrtf(ss / (float)DMODEL + EPSF);
#pragma unroll
    for (int i = 0; i < 4; i++) h[t + 512 * i] += v[i] * inv * w[t + 512 * i];
}

// h += rms(raw)*w1 ; hn = rms(h_new)*w2   (fused: two block reductions)
__global__ void k_rms_add_norm(const float* __restrict__ raw, const float* __restrict__ w1,
                               float* __restrict__ h, const float* __restrict__ w2,
                               float* __restrict__ hn) {
    int t = threadIdx.x;
    float v[4], hv[4];
    float ss = 0.f;
#pragma unroll
    for (int i = 0; i < 4; i++) { v[i] = raw[t + 512 * i]; ss += v[i] * v[i]; }
    ss = block_sum(ss);
    float inv = rsqrtf(ss / (float)DMODEL + EPSF);
    float ss2 = 0.f;
#pragma unroll
    for (int i = 0; i < 4; i++) {
        hv[i] = h[t + 512 * i] + v[i] * inv * w1[t + 512 * i];
        ss2 += hv[i] * hv[i];
    }
    ss2 = block_sum(ss2);
    float inv2 = rsqrtf(ss2 / (float)DMODEL + EPSF);
#pragma unroll
    for (int i = 0; i < 4; i++) {
        h[t + 512 * i] = hv[i];
        hn[t + 512 * i] = hv[i] * inv2 * w2[t + 512 * i];
    }
}

// h = (h + rms(raw)*w) * sc[0]
__global__ void k_rms_add_scale(const float* __restrict__ raw, const float* __restrict__ w,
                                const float* __restrict__ sc, float* __restrict__ h) {
    int t = threadIdx.x;
    float v[4];
    float ss = 0.f;
#pragma unroll
    for (int i = 0; i < 4; i++) { v[i] = raw[t + 512 * i]; ss += v[i] * v[i]; }
    ss = block_sum(ss);
    float inv = rsqrtf(ss / (float)DMODEL + EPSF);
    float s = sc[0];
#pragma unroll
    for (int i = 0; i < 4; i++)
        h[t + 512 * i] = (h[t + 512 * i] + v[i] * inv * w[t + 512 * i]) * s;
}

// generic gemv: y[row] = W[row,:] . x ; warp per row, 8 rows/block, x in smem
template <int DIM>
__global__ void k_gemv(const float* __restrict__ W, const float* __restrict__ x,
                       float* __restrict__ y) {
    __shared__ float4 xs[DIM / 4];
    int t = threadIdx.x;
    for (int i = t; i < DIM / 4; i += 256) xs[i] = ((const float4*)x)[i];
    __syncthreads();
    int warp = t >> 5, lane = t & 31;
    int row = blockIdx.x * 8 + warp;
    const float4* wr = (const float4*)(W + (size_t)row * DIM);
    float s = 0.f;
#pragma unroll 8
    for (int k = 0; k < DIM / 128; k++) {
        float4 a = wr[lane + 32 * k];
        float4 b = xs[lane + 32 * k];
        s += a.x * b.x + a.y * b.y + a.z * b.z + a.w * b.w;
    }
    s = warp_sum(s);
    if (lane == 0) y[row] = s;
}

// fused q/k/v projection: 3072 rows
__global__ void k_gemv_qkv(const float* __restrict__ Wq, const float* __restrict__ Wk,
                           const float* __restrict__ Wv, const float* __restrict__ x,
                           float* __restrict__ y) {
    __shared__ float4 xs[DMODEL / 4];
    int t = threadIdx.x;
    for (int i = t; i < DMODEL / 4; i += 256) xs[i] = ((const float4*)x)[i];
    __syncthreads();
    int warp = t >> 5, lane = t & 31;
    int row = blockIdx.x * 8 + warp;
    const float* W;
    int r;
    if (row < 2048) { W = Wq; r = row; }
    else if (row < 2560) { W = Wk; r = row - 2048; }
    else { W = Wv; r = row - 2560; }
    const float4* wr = (const float4*)(W + (size_t)r * DMODEL);
    float s = 0.f;
#pragma unroll 8
    for (int k = 0; k < DMODEL / 128; k++) {
        float4 a = wr[lane + 32 * k];
        float4 b = xs[lane + 32 * k];
        s += a.x * b.x + a.y * b.y + a.z * b.z + a.w * b.w;
    }
    s = warp_sum(s);
    if (lane == 0) y[row] = s;
}

// fused gate/up: act[row] = gelu(Wg[row].x) * (Wu[row].x)
__global__ void k_gemv_gateup(const float* __restrict__ Wg, const float* __restrict__ Wu,
                              const float* __restrict__ x, float* __restrict__ act) {
    __shared__ float4 xs[DMODEL / 4];
    int t = threadIdx.x;
    for (int i = t; i < DMODEL / 4; i += 256) xs[i] = ((const float4*)x)[i];
    __syncthreads();
    int warp = t >> 5, lane = t & 31;
    int row = blockIdx.x * 8 + warp;
    const float4* wg = (const float4*)(Wg + (size_t)row * DMODEL);
    const float4* wu = (const float4*)(Wu + (size_t)row * DMODEL);
    float sg = 0.f, su = 0.f;
#pragma unroll 8
    for (int k = 0; k < DMODEL / 128; k++) {
        float4 b = xs[lane + 32 * k];
        float4 a = wg[lane + 32 * k];
        sg += a.x * b.x + a.y * b.y + a.z * b.z + a.w * b.w;
        float4 c = wu[lane + 32 * k];
        su += c.x * b.x + c.y * b.y + c.z * b.z + c.w * b.w;
    }
    sg = warp_sum(sg);
    su = warp_sum(su);
    if (lane == 0) act[row] = gelu_t(sg) * su;
}

// per-layer gate gemv: y[row] = gelu(W[row].x) * pl[row]
__global__ void k_gemv_plg(const float* __restrict__ W, const float* __restrict__ x,
                           const float* __restrict__ pl, float* __restrict__ y) {
    __shared__ float4 xs[DMODEL / 4];
    int t = threadIdx.x;
    for (int i = t; i < DMODEL / 4; i += 256) xs[i] = ((const float4*)x)[i];
    __syncthreads();
    int warp = t >> 5, lane = t & 31;
    int row = blockIdx.x * 8 + warp;
    const float4* wr = (const float4*)(W + (size_t)row * DMODEL);
    float s = 0.f;
#pragma unroll 8
    for (int k = 0; k < DMODEL / 128; k++) {
        float4 a = wr[lane + 32 * k];
        float4 b = xs[lane + 32 * k];
        s += a.x * b.x + a.y * b.y + a.z * b.z + a.w * b.w;
    }
    s = warp_sum(s);
    if (lane == 0) y[row] = gelu_t(s) * pl[row];
}

// per-head rms norm + (qn/kn) scale + rope; writes q/knew/vnew; k,v also to out KV row
// block b: 0..7 q heads, 8..9 k heads, 10..11 v heads; 256 threads
__global__ void k_hnr(const float* __restrict__ qkv, const float* __restrict__ qn,
                      const float* __restrict__ kn, const float* __restrict__ cosp,
                      const float* __restrict__ sinp, float* __restrict__ q,
                      float* __restrict__ knew, float* __restrict__ vnew,
                      float* __restrict__ outK_l, float* __restrict__ outV_l) {
    int b = blockIdx.x, t = threadIdx.x;
    float x = qkv[b * 256 + t];
    float ss = block_sum(x * x);
    float inv = rsqrtf(ss / (float)HDIM + EPSF);
    __shared__ float sv[256];
    float val;
    if (b < 8) val = x * inv * qn[t];
    else if (b < 10) val = x * inv * kn[t];
    else val = x * inv;
    sv[t] = val;
    __syncthreads();
    float out;
    if (b < 10) {
        float other = (t < 128) ? -sv[t + 128] : sv[t - 128];
        out = val * cosp[t] + other * sinp[t];
    } else {
        out = val;
    }
    if (b < 8) {
        q[b * 256 + t] = out;
    } else if (b < 10) {
        int kv = b - 8;
        knew[kv * 256 + t] = out;
        outK_l[((size_t)kv * SEQ + POS) * HDIM + t] = out;
    } else {
        int kv = b - 10;
        vnew[kv * 256 + t] = out;
        outV_l[((size_t)kv * SEQ + POS) * HDIM + t] = out;
    }
}

// attention scores: grid (8 heads, 17 chunks of 128 positions), 256 threads (8 warps)
__global__ void k_scores(const float* __restrict__ q, const float* __restrict__ Kl,
                         const float* __restrict__ knew, float* __restrict__ scores) {
    int h = blockIdx.x, c = blockIdx.y, t = threadIdx.x;
    int kv = h >> 2;
    __shared__ float4 qs[64];
    if (t < 64) qs[t] = ((const float4*)(q + h * 256))[t];
    __syncthreads();
    int warp = t >> 5, lane = t & 31;
    const float* Kbase = Kl + (size_t)kv * SEQ * HDIM;
    const float* knv = knew + kv * HDIM;
    int s0 = c * 128;
#pragma unroll
    for (int i = 0; i < 16; i++) {
        int s = s0 + i * 8 + warp;
        if (s <= POS) {
            const float4* kr = (s == POS) ? (const float4*)knv
                                          : (const float4*)(Kbase + (size_t)s * HDIM);
            float4 a = kr[lane], b = qs[lane];
            float acc = a.x * b.x + a.y * b.y + a.z * b.z + a.w * b.w;
            a = kr[lane + 32]; b = qs[lane + 32];
            acc += a.x * b.x + a.y * b.y + a.z * b.z + a.w * b.w;
            acc = warp_sum(acc);
            if (lane == 0) scores[h * SSTR + s] = acc;
        }
    }
}

// softmax per head over NS positions; also zeroes attn accumulator
__global__ void k_softmax(float* __restrict__ scores, float* __restrict__ attn) {
    int h = blockIdx.x, t = threadIdx.x;
    __shared__ float sh[NS];
    float m = -3.0e38f;
    for (int s = t; s < NS; s += 256) {
        float v = scores[h * SSTR + s];
        sh[s] = v;
        m = fmaxf(m, v);
    }
    m = block_max(m);
    float sum = 0.f;
    for (int s = t; s < NS; s += 256) {
        float e = __expf(sh[s] - m);
        sh[s] = e;
        sum += e;
    }
    sum = block_sum(sum);
    float invz = 1.f / sum;
    for (int s = t; s < NS; s += 256) scores[h * SSTR + s] = sh[s] * invz;
    attn[h * HDIM + t] = 0.f;
}

// attn[h,d] += sum over chunk of p[s]*V[s,d]; grid (8, 17), 256 threads (= d)
__global__ void k_attnv(const float* __restrict__ scores, const float* __restrict__ Vl,
                        const float* __restrict__ vnew, float* __restrict__ attn) {
    int h = blockIdx.x, c = blockIdx.y, t = threadIdx.x;
    int kv = h >> 2;
    __shared__ float ps[128];
    int s0 = c * 128;
    if (t < 128) {
        int s = s0 + t;
        ps[t] = (s <= POS) ? scores[h * SSTR + s] : 0.f;
    }
    __syncthreads();
    const float* Vbase = Vl + (size_t)kv * SEQ * HDIM;
    const float* vnv = vnew + kv * HDIM;
    float acc = 0.f;
#pragma unroll 4
    for (int i = 0; i < 128; i++) {
        int s = s0 + i;
        const float* vr = (s == POS) ? vnv : (Vbase + (size_t)s * HDIM);
        acc += ps[i] * vr[t];
    }
    atomicAdd(&attn[h * HDIM + t], acc);
}

// ---------------- host launcher ----------------
extern "C" void kernel_launch(void* const* d_in, const int* in_sizes, int n_in,
                              void* d_out, int out_size) {
    const float* hs    = (const float*)d_in[0];
    const float* pls   = (const float*)d_in[3];
    const float* cos_s = (const float*)d_in[4];
    const float* sin_s = (const float*)d_in[5];
    const float* cos_f = (const float*)d_in[6];
    const float* sin_f = (const float*)d_in[7];
    const float* K_in  = (const float*)d_in[8];
    const float* V_in  = (const float*)d_in[9];
    const float* Wq    = (const float*)d_in[10];
    const float* Wk    = (const float*)d_in[11];
    const float* Wv    = (const float*)d_in[12];
    const float* Wo    = (const float*)d_in[13];
    const float* qn    = (const float*)d_in[14];
    const float* kn    = (const float*)d_in[15];
    const float* ln_in   = (const float*)d_in[16];
    const float* ln_pa   = (const float*)d_in[17];
    const float* ln_pre  = (const float*)d_in[18];
    const float* ln_post = (const float*)d_in[19];
    const float* ln_pl   = (const float*)d_in[20];
    const float* Wg    = (const float*)d_in[21];
    const float* Wu    = (const float*)d_in[22];
    const float* Wd    = (const float*)d_in[23];
    const float* Wplg  = (const float*)d_in[24];
    const float* Wplp  = (const float*)d_in[25];
    const float* lsc   = (const float*)d_in[26];

    float* out = (float*)d_out;
    const size_t kvsz = (size_t)NLAYER * NKV * SEQ * HDIM;  // 16,777,216
    float* outK = out + DMODEL;
    float* outV = outK + kvsz;

    float* sb = nullptr;
    cudaGetSymbolAddress((void**)&sb, g_scratch);
    float* b_h    = sb + OFF_H;
    float* b_hn   = sb + OFF_HN;
    float* b_qkv  = sb + OFF_QKV;
    float* b_q    = sb + OFF_Q;
    float* b_knew = sb + OFF_KNEW;
    float* b_vnew = sb + OFF_VNEW;
    float* b_attn = sb + OFF_ATTN;
    float* b_act  = sb + OFF_ACT;
    float* b_vec  = sb + OFF_VEC;
    float* b_g2   = sb + OFF_G2;
    float* b_sc   = sb + OFF_SC;

    // bulk KV copy (old cache -> output); updated rows overwritten per-layer below
    k_copy_kv<<<4096, 256>>>((const float4*)K_in, (const float4*)V_in,
                             (float4*)outK, (float4*)outV, (int)(kvsz / 4));
    // h = hidden_states
    k_copy<<<8, 256>>>(hs, b_h, DMODEL);

    for (int l = 0; l < NLAYER; l++) {
        const float* Wq_l = Wq + (size_t)l * 2048 * 2048;
        const float* Wk_l = Wk + (size_t)l * 512 * 2048;
        const float* Wv_l = Wv + (size_t)l * 512 * 2048;
        const float* Wo_l = Wo + (size_t)l * 2048 * 2048;
        const float* Wg_l = Wg + (size_t)l * 8192 * 2048;
        const float* Wu_l = Wu + (size_t)l * 8192 * 2048;
        const float* Wd_l = Wd + (size_t)l * 2048 * 8192;
        const float* Wplg_l = Wplg + (size_t)l * 256 * 2048;
        const float* Wplp_l = Wplp + (size_t)l * 2048 * 256;
        const float* K_l = K_in + (size_t)l * NKV * SEQ * HDIM;
        const float* V_l = V_in + (size_t)l * NKV * SEQ * HDIM;
        float* outK_l = outK + (size_t)l * NKV * SEQ * HDIM;
        float* outV_l = outV + (size_t)l * NKV * SEQ * HDIM;
        bool full = ((l + 1) % 5) == 0;
        const float* cp = full ? cos_f : cos_s;
        const float* sp = full ? sin_f : sin_s;

        // attention block
        k_rms_scale<<<1, 512>>>(b_h, ln_in + l * DMODEL, b_hn);
        k_gemv_qkv<<<384, 256>>>(Wq_l, Wk_l, Wv_l, b_hn, b_qkv);
        k_hnr<<<12, 256>>>(b_qkv, qn + l * HDIM, kn + l * HDIM, cp, sp,
                           b_q, b_knew, b_vnew, outK_l, outV_l);
        k_scores<<<dim3(8, 17), 256>>>(b_q, K_l, b_knew, b_sc);
        k_softmax<<<8, 256>>>(b_sc, b_attn);
        k_attnv<<<dim3(8, 17), 256>>>(b_sc, V_l, b_vnew, b_attn);
        k_gemv<2048><<<256, 256>>>(Wo_l, b_attn, b_vec);
        k_rms_add_norm<<<1, 512>>>(b_vec, ln_pa + l * DMODEL, b_h,
                                   ln_pre + l * DMODEL, b_hn);
        // MLP block
        k_gemv_gateup<<<1024, 256>>>(Wg_l, Wu_l, b_hn, b_act);
        k_gemv<8192><<<256, 256>>>(Wd_l, b_act, b_vec);
        k_rms_add<<<1, 512>>>(b_vec, ln_post + l * DMODEL, b_h);
        // per-layer block
        k_gemv_plg<<<32, 256>>>(Wplg_l, b_h, pls + l * PLDIM, b_g2);
        k_gemv<256><<<256, 256>>>(Wplp_l, b_g2, b_vec);
        k_rms_add_scale<<<1, 512>>>(b_vec, ln_pl + l * DMODEL, lsc + l, b_h);
    }

    // final hidden state
    k_copy<<<8, 256>>>(b_h, out, DMODEL);
}

// round 2
// speedup vs baseline: 1.1993x; 1.1993x over previous
#include <cuda_runtime.h>
#include <cstddef>

#define NLAYER 8
#define DMODEL 2048
#define NHEAD 8
#define NKV 2
#define HDIM 256
#define SEQ 4096
#define FFDIM 8192
#define PLDIM 256
#define POS 2048
#define NS 2049          // valid attention positions (0..POS)
#define SSTR 2080        // padded score row stride
#define EPSF 1e-6f

// ---------------- scratch (device global, no allocation) ----------------
#define OFF_H     0
#define OFF_HN    2048
#define OFF_Q     4096
#define OFF_KNEW  6144
#define OFF_VNEW  6656
#define OFF_ATTN  7168
#define OFF_ACT   9216
#define OFF_G2    17408
#define OFF_SC    17664              // 8*2080 = 16640
#define OFF_PART  34304              // up to 16384 (Wd split-8 partials)
__device__ __align__(16) float g_scratch[34304 + 16384];

// ---------------- helpers ----------------
__device__ __forceinline__ float warp_sum(float v) {
#pragma unroll
    for (int o = 16; o; o >>= 1) v += __shfl_xor_sync(0xffffffffu, v, o);
    return v;
}
__device__ __forceinline__ float warp_max(float v) {
#pragma unroll
    for (int o = 16; o; o >>= 1) v = fmaxf(v, __shfl_xor_sync(0xffffffffu, v, o));
    return v;
}
__device__ __forceinline__ float block_sum(float v) {
    __shared__ float red[16];
    __shared__ float tot;
    int t = threadIdx.x, nw = (int)(blockDim.x >> 5);
    __syncthreads();
    v = warp_sum(v);
    if ((t & 31) == 0) red[t >> 5] = v;
    __syncthreads();
    if (t < 32) {
        float s = (t < nw) ? red[t] : 0.f;
        s = warp_sum(s);
        if (t == 0) tot = s;
    }
    __syncthreads();
    return tot;
}
__device__ __forceinline__ float block_max(float v) {
    __shared__ float red[16];
    __shared__ float tot;
    int t = threadIdx.x, nw = (int)(blockDim.x >> 5);
    __syncthreads();
    v = warp_max(v);
    if ((t & 31) == 0) red[t >> 5] = v;
    __syncthreads();
    if (t < 32) {
        float s = (t < nw) ? red[t] : -3.0e38f;
        s = warp_max(s);
        if (t == 0) tot = s;
    }
    __syncthreads();
    return tot;
}
__device__ __forceinline__ float gelu_t(float x) {
    float x3 = x * x * x;
    return 0.5f * x * (1.f + tanhf(0.7978845608028654f * (x + 0.044715f * x3)));
}
__device__ __forceinline__ float dot4(float4 a, float4 b) {
    return a.x * b.x + a.y * b.y + a.z * b.z + a.w * b.w;
}

// ---------------- kernels ----------------

// big KV copy: K_in,V_in -> out (float4 grid-stride)
__global__ void k_copy_kv(const float4* __restrict__ a, const float4* __restrict__ b,
                          float4* __restrict__ oa, float4* __restrict__ ob, int n4) {
    int i = blockIdx.x * blockDim.x + threadIdx.x;
    int stride = gridDim.x * blockDim.x;
    for (; i < n4; i += stride) {
        oa[i] = a[i];
        ob[i] = b[i];
    }
}

__global__ void k_copy(const float* __restrict__ src, float* __restrict__ dst, int n) {
    int i = blockIdx.x * blockDim.x + threadIdx.x;
    if (i < n) dst[i] = src[i];
}

// out = rms(x)*w   (1 block, 512 threads, D=2048)
__global__ void k_rms_scale(const float* __restrict__ x, const float* __restrict__ w,
                            float* __restrict__ out) {
    int t = threadIdx.x;
    float v[4];
    float ss = 0.f;
#pragma unroll
    for (int i = 0; i < 4; i++) { v[i] = x[t + 512 * i]; ss += v[i] * v[i]; }
    ss = block_sum(ss);
    float inv = rsqrtf(ss / (float)DMODEL + EPSF);
#pragma unroll
    for (int i = 0; i < 4; i++) out[t + 512 * i] = v[i] * inv * w[t + 512 * i];
}

// h += rms(sum partials)*w
template <int NSPLIT>
__global__ void k_rms_add(const float* __restrict__ part, const float* __restrict__ w,
                          float* __restrict__ h) {
    int t = threadIdx.x;
    float v[4];
    float ss = 0.f;
#pragma unroll
    for (int i = 0; i < 4; i++) {
        int j = t + 512 * i;
        float r = 0.f;
#pragma unroll
        for (int s = 0; s < NSPLIT; s++) r += part[s * DMODEL + j];
        v[i] = r;
        ss += r * r;
    }
    ss = block_sum(ss);
    float inv = rsqrtf(ss / (float)DMODEL + EPSF);
#pragma unroll
    for (int i = 0; i < 4; i++) h[t + 512 * i] += v[i] * inv * w[t + 512 * i];
}

// h += rms(sum partials)*w1 ; hn = rms(h_new)*w2
template <int NSPLIT>
__global__ void k_rms_add_norm(const float* __restrict__ part, const float* __restrict__ w1,
                               float* __restrict__ h, const float* __restrict__ w2,
                               float* __restrict__ hn) {
    int t = threadIdx.x;
    float v[4], hv[4];
    float ss = 0.f;
#pragma unroll
    for (int i = 0; i < 4; i++) {
        int j = t + 512 * i;
        float r = 0.f;
#pragma unroll
        for (int s = 0; s < NSPLIT; s++) r += part[s * DMODEL + j];
        v[i] = r;
        ss += r * r;
    }
    ss = block_sum(ss);
    float inv = rsqrtf(ss / (float)DMODEL + EPSF);
    float ss2 = 0.f;
#pragma unroll
    for (int i = 0; i < 4; i++) {
        hv[i] = h[t + 512 * i] + v[i] * inv * w1[t + 512 * i];
        ss2 += hv[i] * hv[i];
    }
    ss2 = block_sum(ss2);
    float inv2 = rsqrtf(ss2 / (float)DMODEL + EPSF);
#pragma unroll
    for (int i = 0; i < 4; i++) {
        h[t + 512 * i] = hv[i];
        hn[t + 512 * i] = hv[i] * inv2 * w2[t + 512 * i];
    }
}

// h = (h + rms(raw)*w) * sc[0] ; hn = rms(h_new)*w2   (fused tail + next-layer input norm)
__global__ void k_rms_add_scale_norm(const float* __restrict__ raw, const float* __restrict__ w,
                                     const float* __restrict__ sc, float* __restrict__ h,
                                     const float* __restrict__ w2, float* __restrict__ hn) {
    int t = threadIdx.x;
    float v[4], hv[4];
    float ss = 0.f;
#pragma unroll
    for (int i = 0; i < 4; i++) { v[i] = raw[t + 512 * i]; ss += v[i] * v[i]; }
    ss = block_sum(ss);
    float inv = rsqrtf(ss / (float)DMODEL + EPSF);
    float s = sc[0];
    float ss2 = 0.f;
#pragma unroll
    for (int i = 0; i < 4; i++) {
        hv[i] = (h[t + 512 * i] + v[i] * inv * w[t + 512 * i]) * s;
        ss2 += hv[i] * hv[i];
    }
    ss2 = block_sum(ss2);
    float inv2 = rsqrtf(ss2 / (float)DMODEL + EPSF);
#pragma unroll
    for (int i = 0; i < 4; i++) {
        h[t + 512 * i] = hv[i];
        hn[t + 512 * i] = hv[i] * inv2 * w2[t + 512 * i];
    }
}

// K-split gemv: ypart[chunk][row] = W[row, chunk*KCH : (chunk+1)*KCH] . x[chunk]
// warp per row-chunk, 8 rows/block, grid (rows/8, NSPLIT)
template <int DIM, int NSPLIT>
__global__ void k_gemv_split(const float* __restrict__ W, const float* __restrict__ x,
                             float* __restrict__ ypart) {
    constexpr int KCH = DIM / NSPLIT;
    __shared__ float4 xs[KCH / 4];
    int t = threadIdx.x;
    int c = blockIdx.y;
    const float4* xp = (const float4*)(x + c * KCH);
    for (int i = t; i < KCH / 4; i += 256) xs[i] = xp[i];
    __syncthreads();
    int warp = t >> 5, lane = t & 31;
    int row = blockIdx.x * 8 + warp;
    const float4* wr = (const float4*)(W + (size_t)row * DIM + c * KCH);
    float acc0 = 0.f, acc1 = 0.f;
#pragma unroll
    for (int k = 0; k < KCH / 256; k++) {
        float4 a0 = __ldcs(wr + lane + 64 * k);
        float4 a1 = __ldcs(wr + lane + 32 + 64 * k);
        acc0 += dot4(a0, xs[lane + 64 * k]);
        acc1 += dot4(a1, xs[lane + 32 + 64 * k]);
    }
    float s = warp_sum(acc0 + acc1);
    int rows = gridDim.x * 8;
    if (lane == 0) ypart[c * rows + row] = s;
}

// fused q/k/v projection with K-split: 3072 rows, grid (384, NSPLIT)
template <int NSPLIT>
__global__ void k_gemv_qkv_split(const float* __restrict__ Wq, const float* __restrict__ Wk,
                                 const float* __restrict__ Wv, const float* __restrict__ x,
                                 float* __restrict__ ypart) {
    constexpr int KCH = DMODEL / NSPLIT;
    __shared__ float4 xs[KCH / 4];
    int t = threadIdx.x;
    int c = blockIdx.y;
    const float4* xp = (const float4*)(x + c * KCH);
    for (int i = t; i < KCH / 4; i += 256) xs[i] = xp[i];
    __syncthreads();
    int warp = t >> 5, lane = t & 31;
    int row = blockIdx.x * 8 + warp;
    const float* W;
    int r;
    if (row < 2048) { W = Wq; r = row; }
    else if (row < 2560) { W = Wk; r = row - 2048; }
    else { W = Wv; r = row - 2560; }
    const float4* wr = (const float4*)(W + (size_t)r * DMODEL + c * KCH);
    float acc0 = 0.f, acc1 = 0.f;
#pragma unroll
    for (int k = 0; k < KCH / 256; k++) {
        float4 a0 = __ldcs(wr + lane + 64 * k);
        float4 a1 = __ldcs(wr + lane + 32 + 64 * k);
        acc0 += dot4(a0, xs[lane + 64 * k]);
        acc1 += dot4(a1, xs[lane + 32 + 64 * k]);
    }
    float s = warp_sum(acc0 + acc1);
    if (lane == 0) ypart[c * 3072 + row] = s;
}

// fused gate/up: act[row] = gelu(Wg[row].x) * (Wu[row].x) ; grid 1024
__global__ void k_gemv_gateup(const float* __restrict__ Wg, const float* __restrict__ Wu,
                              const float* __restrict__ x, float* __restrict__ act) {
    __shared__ float4 xs[DMODEL / 4];
    int t = threadIdx.x;
    for (int i = t; i < DMODEL / 4; i += 256) xs[i] = ((const float4*)x)[i];
    __syncthreads();
    int warp = t >> 5, lane = t & 31;
    int row = blockIdx.x * 8 + warp;
    const float4* wg = (const float4*)(Wg + (size_t)row * DMODEL);
    const float4* wu = (const float4*)(Wu + (size_t)row * DMODEL);
    float sg = 0.f, su = 0.f;
#pragma unroll 8
    for (int k = 0; k < DMODEL / 128; k++) {
        float4 b = xs[lane + 32 * k];
        float4 a = __ldcs(wg + lane + 32 * k);
        sg += dot4(a, b);
        float4 cc = __ldcs(wu + lane + 32 * k);
        su += dot4(cc, b);
    }
    sg = warp_sum(sg);
    su = warp_sum(su);
    if (lane == 0) act[row] = gelu_t(sg) * su;
}

// per-layer gate: block per row (256 blocks), y[r] = gelu(W[r].h) * pl[r]
__global__ void k_plg_rowblock(const float* __restrict__ W, const float* __restrict__ x,
                               const float* __restrict__ pl, float* __restrict__ y) {
    int r = blockIdx.x, t = threadIdx.x;
    const float4* wr = (const float4*)(W + (size_t)r * DMODEL);
    const float4* xp = (const float4*)x;
    float s = dot4(__ldcs(wr + t), xp[t]) + dot4(__ldcs(wr + t + 256), xp[t + 256]);
    s = block_sum(s);
    if (t == 0) y[r] = gelu_t(s) * pl[r];
}

// small gemv (plp): warp per row, 8 rows/block
template <int DIM>
__global__ void k_gemv(const float* __restrict__ W, const float* __restrict__ x,
                       float* __restrict__ y) {
    __shared__ float4 xs[DIM / 4];
    int t = threadIdx.x;
    for (int i = t; i < DIM / 4; i += 256) xs[i] = ((const float4*)x)[i];
    __syncthreads();
    int warp = t >> 5, lane = t & 31;
    int row = blockIdx.x * 8 + warp;
    const float4* wr = (const float4*)(W + (size_t)row * DIM);
    float s = 0.f;
#pragma unroll
    for (int k = 0; k < DIM / 128; k++)
        s += dot4(__ldcs(wr + lane + 32 * k), xs[lane + 32 * k]);
    s = warp_sum(s);
    if (lane == 0) y[row] = s;
}

// per-head rms norm + (qn/kn) scale + rope; input = 4-way partial sums
__global__ void k_hnr(const float* __restrict__ qp, const float* __restrict__ qn,
                      const float* __restrict__ kn, const float* __restrict__ cosp,
                      const float* __restrict__ sinp, float* __restrict__ q,
                      float* __restrict__ knew, float* __restrict__ vnew,
                      float* __restrict__ outK_l, float* __restrict__ outV_l) {
    int b = blockIdx.x, t = threadIdx.x;
    int j = b * 256 + t;
    float x = qp[j] + qp[3072 + j] + qp[6144 + j] + qp[9216 + j];
    float ss = block_sum(x * x);
    float inv = rsqrtf(ss / (float)HDIM + EPSF);
    __shared__ float sv[256];
    float val;
    if (b < 8) val = x * inv * qn[t];
    else if (b < 10) val = x * inv * kn[t];
    else val = x * inv;
    sv[t] = val;
    __syncthreads();
    float out;
    if (b < 10) {
        float other = (t < 128) ? -sv[t + 128] : sv[t - 128];
        out = val * cosp[t] + other * sinp[t];
    } else {
        out = val;
    }
    if (b < 8) {
        q[b * 256 + t] = out;
    } else if (b < 10) {
        int kv = b - 8;
        knew[kv * 256 + t] = out;
        outK_l[((size_t)kv * SEQ + POS) * HDIM + t] = out;
    } else {
        int kv = b - 10;
        vnew[kv * 256 + t] = out;
        outV_l[((size_t)kv * SEQ + POS) * HDIM + t] = out;
    }
}

// attention scores: grid (8 heads, 33 chunks of 64), 256 threads (8 warps)
__global__ void k_scores(const float* __restrict__ q, const float* __restrict__ Kl,
                         const float* __restrict__ knew, float* __restrict__ scores) {
    int h = blockIdx.x, c = blockIdx.y, t = threadIdx.x;
    int kv = h >> 2;
    __shared__ float4 qs[64];
    if (t < 64) qs[t] = ((const float4*)(q + h * 256))[t];
    __syncthreads();
    int warp = t >> 5, lane = t & 31;
    const float* Kbase = Kl + (size_t)kv * SEQ * HDIM;
    const float* knv = knew + kv * HDIM;
    int s0 = c * 64;
#pragma unroll
    for (int i = 0; i < 8; i++) {
        int s = s0 + i * 8 + warp;
        if (s <= POS) {
            const float4* kr = (s == POS) ? (const float4*)knv
                                          : (const float4*)(Kbase + (size_t)s * HDIM);
            float acc = dot4(kr[lane], qs[lane]) + dot4(kr[lane + 32], qs[lane + 32]);
            acc = warp_sum(acc);
            if (lane == 0) scores[h * SSTR + s] = acc;
        }
    }
}

// softmax per head over NS positions; also zeroes attn accumulator
__global__ void k_softmax(float* __restrict__ scores, float* __restrict__ attn) {
    int h = blockIdx.x, t = threadIdx.x;
    __shared__ float sh[NS];
    float m = -3.0e38f;
    for (int s = t; s < NS; s += 256) {
        float v = scores[h * SSTR + s];
        sh[s] = v;
        m = fmaxf(m, v);
    }
    m = block_max(m);
    float sum = 0.f;
    for (int s = t; s < NS; s += 256) {
        float e = __expf(sh[s] - m);
        sh[s] = e;
        sum += e;
    }
    sum = block_sum(sum);
    float invz = 1.f / sum;
    for (int s = t; s < NS; s += 256) scores[h * SSTR + s] = sh[s] * invz;
    attn[h * HDIM + t] = 0.f;
}

// attn[h,d] += sum over chunk of p[s]*V[s,d]; grid (8, 33), 256 threads (= d)
__global__ void k_attnv(const float* __restrict__ scores, const float* __restrict__ Vl,
                        const float* __restrict__ vnew, float* __restrict__ attn) {
    int h = blockIdx.x, c = blockIdx.y, t = threadIdx.x;
    int kv = h >> 2;
    __shared__ float ps[64];
    int s0 = c * 64;
    if (t < 64) {
        int s = s0 + t;
        ps[t] = (s <= POS) ? scores[h * SSTR + s] : 0.f;
    }
    __syncthreads();
    const float* Vbase = Vl + (size_t)kv * SEQ * HDIM;
    const float* vnv = vnew + kv * HDIM;
    float acc = 0.f;
#pragma unroll 4
    for (int i = 0; i < 64; i++) {
        int s = s0 + i;
        const float* vr = (s == POS) ? vnv : (Vbase + (size_t)s * HDIM);
        acc += ps[i] * vr[t];
    }
    atomicAdd(&attn[h * HDIM + t], acc);
}

// ---------------- host launcher ----------------
extern "C" void kernel_launch(void* const* d_in, const int* in_sizes, int n_in,
                              void* d_out, int out_size) {
    const float* hs    = (const float*)d_in[0];
    const float* pls   = (const float*)d_in[3];
    const float* cos_s = (const float*)d_in[4];
    const float* sin_s = (const float*)d_in[5];
    const float* cos_f = (const float*)d_in[6];
    const float* sin_f = (const float*)d_in[7];
    const float* K_in  = (const float*)d_in[8];
    const float* V_in  = (const float*)d_in[9];
    const float* Wq    = (const float*)d_in[10];
    const float* Wk    = (const float*)d_in[11];
    const float* Wv    = (const float*)d_in[12];
    const float* Wo    = (const float*)d_in[13];
    const float* qn    = (const float*)d_in[14];
    const float* kn    = (const float*)d_in[15];
    const float* ln_in   = (const float*)d_in[16];
    const float* ln_pa   = (const float*)d_in[17];
    const float* ln_pre  = (const float*)d_in[18];
    const float* ln_post = (const float*)d_in[19];
    const float* ln_pl   = (const float*)d_in[20];
    const float* Wg    = (const float*)d_in[21];
    const float* Wu    = (const float*)d_in[22];
    const float* Wd    = (const float*)d_in[23];
    const float* Wplg  = (const float*)d_in[24];
    const float* Wplp  = (const float*)d_in[25];
    const float* lsc   = (const float*)d_in[26];

    float* out = (float*)d_out;
    const size_t kvsz = (size_t)NLAYER * NKV * SEQ * HDIM;  // 16,777,216
    float* outK = out + DMODEL;
    float* outV = outK + kvsz;

    float* sb = nullptr;
    cudaGetSymbolAddress((void**)&sb, g_scratch);
    float* b_h    = sb + OFF_H;
    float* b_hn   = sb + OFF_HN;
    float* b_q    = sb + OFF_Q;
    float* b_knew = sb + OFF_KNEW;
    float* b_vnew = sb + OFF_VNEW;
    float* b_attn = sb + OFF_ATTN;
    float* b_act  = sb + OFF_ACT;
    float* b_g2   = sb + OFF_G2;
    float* b_sc   = sb + OFF_SC;
    float* b_part = sb + OFF_PART;

    // bulk KV copy (old cache -> output); updated rows overwritten per-layer below
    k_copy_kv<<<4096, 256>>>((const float4*)K_in, (const float4*)V_in,
                             (float4*)outK, (float4*)outV, (int)(kvsz / 4));
    // h = hidden_states ; hn = rms(h)*ln_in[0]
    k_copy<<<8, 256>>>(hs, b_h, DMODEL);
    k_rms_scale<<<1, 512>>>(b_h, ln_in, b_hn);

    for (int l = 0; l < NLAYER; l++) {
        const float* Wq_l = Wq + (size_t)l * 2048 * 2048;
        const float* Wk_l = Wk + (size_t)l * 512 * 2048;
        const float* Wv_l = Wv + (size_t)l * 512 * 2048;
        const float* Wo_l = Wo + (size_t)l * 2048 * 2048;
        const float* Wg_l = Wg + (size_t)l * 8192 * 2048;
        const float* Wu_l = Wu + (size_t)l * 8192 * 2048;
        const float* Wd_l = Wd + (size_t)l * 2048 * 8192;
        const float* Wplg_l = Wplg + (size_t)l * 256 * 2048;
        const float* Wplp_l = Wplp + (size_t)l * 2048 * 256;
        const float* K_l = K_in + (size_t)l * NKV * SEQ * HDIM;
        const float* V_l = V_in + (size_t)l * NKV * SEQ * HDIM;
        float* outK_l = outK + (size_t)l * NKV * SEQ * HDIM;
        float* outV_l = outV + (size_t)l * NKV * SEQ * HDIM;
        bool full = ((l + 1) % 5) == 0;
        const float* cp = full ? cos_f : cos_s;
        const float* sp = full ? sin_f : sin_s;
        // ln_in weight for NEXT layer (used by the fused tail norm)
        const float* ln_in_next = ln_in + ((l + 1 < NLAYER) ? (l + 1) : 0) * DMODEL;

        // attention block
        k_gemv_qkv_split<4><<<dim3(384, 4), 256>>>(Wq_l, Wk_l, Wv_l, b_hn, b_part);
        k_hnr<<<12, 256>>>(b_part, qn + l * HDIM, kn + l * HDIM, cp, sp,
                           b_q, b_knew, b_vnew, outK_l, outV_l);
        k_scores<<<dim3(8, 33), 256>>>(b_q, K_l, b_knew, b_sc);
        k_softmax<<<8, 256>>>(b_sc, b_attn);
        k_attnv<<<dim3(8, 33), 256>>>(b_sc, V_l, b_vnew, b_attn);
        k_gemv_split<2048, 4><<<dim3(256, 4), 256>>>(Wo_l, b_attn, b_part);
        k_rms_add_norm<4><<<1, 512>>>(b_part, ln_pa + l * DMODEL, b_h,
                                      ln_pre + l * DMODEL, b_hn);
        // MLP block
        k_gemv_gateup<<<1024, 256>>>(Wg_l, Wu_l, b_hn, b_act);
        k_gemv_split<8192, 8><<<dim3(256, 8), 256>>>(Wd_l, b_act, b_part);
        k_rms_add<8><<<1, 512>>>(b_part, ln_post + l * DMODEL, b_h);
        // per-layer block
        k_plg_rowblock<<<256, 256>>>(Wplg_l, b_h, pls + l * PLDIM, b_g2);
        k_gemv<256><<<256, 256>>>(Wplp_l, b_g2, b_part);
        k_rms_add_scale_norm<<<1, 512>>>(b_part, ln_pl + l * DMODEL, lsc + l,
                                         b_h, ln_in_next, b_hn);
    }

    // final hidden state
    k_copy<<<8, 256>>>(b_h, out, DMODEL);
}

// round 3
// speedup vs baseline: 1.2058x; 1.0054x over previous
#include <cuda_runtime.h>
#include <cstddef>

#define NLAYER 8
#define DMODEL 2048
#define NHEAD 8
#define NKV 2
#define HDIM 256
#define SEQ 4096
#define FFDIM 8192
#define PLDIM 256
#define POS 2048
#define NS 2049          // valid attention positions (0..POS)
#define SSTR 2080        // padded score row stride
#define EPSF 1e-6f
#define NBLK 512         // one-wave persistent grid for weight GEMVs

// ---------------- scratch (device global, no allocation) ----------------
#define OFF_H     0
#define OFF_HN    2048
#define OFF_Q     4096
#define OFF_KNEW  6144
#define OFF_VNEW  6656
#define OFF_ATTN  7168
#define OFF_ACT   9216
#define OFF_G2    17408
#define OFF_SC    17664              // 8*2080 = 16640
#define OFF_PART  34304              // up to 16384 (Wd split-8 partials)
__device__ __align__(16) float g_scratch[34304 + 16384];

// ---------------- helpers ----------------
__device__ __forceinline__ float warp_sum(float v) {
#pragma unroll
    for (int o = 16; o; o >>= 1) v += __shfl_xor_sync(0xffffffffu, v, o);
    return v;
}
__device__ __forceinline__ float warp_max(float v) {
#pragma unroll
    for (int o = 16; o; o >>= 1) v = fmaxf(v, __shfl_xor_sync(0xffffffffu, v, o));
    return v;
}
__device__ __forceinline__ float block_sum(float v) {
    __shared__ float red[16];
    __shared__ float tot;
    int t = threadIdx.x, nw = (int)(blockDim.x >> 5);
    __syncthreads();
    v = warp_sum(v);
    if ((t & 31) == 0) red[t >> 5] = v;
    __syncthreads();
    if (t < 32) {
        float s = (t < nw) ? red[t] : 0.f;
        s = warp_sum(s);
        if (t == 0) tot = s;
    }
    __syncthreads();
    return tot;
}
__device__ __forceinline__ float block_max(float v) {
    __shared__ float red[16];
    __shared__ float tot;
    int t = threadIdx.x, nw = (int)(blockDim.x >> 5);
    __syncthreads();
    v = warp_max(v);
    if ((t & 31) == 0) red[t >> 5] = v;
    __syncthreads();
    if (t < 32) {
        float s = (t < nw) ? red[t] : -3.0e38f;
        s = warp_max(s);
        if (t == 0) tot = s;
    }
    __syncthreads();
    return tot;
}
__device__ __forceinline__ float gelu_t(float x) {
    float x3 = x * x * x;
    return 0.5f * x * (1.f + tanhf(0.7978845608028654f * (x + 0.044715f * x3)));
}
__device__ __forceinline__ float dot4(float4 a, float4 b) {
    return a.x * b.x + a.y * b.y + a.z * b.z + a.w * b.w;
}

// ---------------- kernels ----------------

// big KV copy: K_in,V_in -> out (float4 grid-stride, one wave)
__global__ void k_copy_kv(const float4* __restrict__ a, const float4* __restrict__ b,
                          float4* __restrict__ oa, float4* __restrict__ ob, int n4) {
    int i = blockIdx.x * blockDim.x + threadIdx.x;
    int stride = gridDim.x * blockDim.x;
    for (; i < n4; i += stride) {
        oa[i] = a[i];
        ob[i] = b[i];
    }
}

__global__ void k_copy(const float* __restrict__ src, float* __restrict__ dst, int n) {
    int i = blockIdx.x * blockDim.x + threadIdx.x;
    if (i < n) dst[i] = src[i];
}

// out = rms(x)*w   (1 block, 512 threads, D=2048)
__global__ void k_rms_scale(const float* __restrict__ x, const float* __restrict__ w,
                            float* __restrict__ out) {
    int t = threadIdx.x;
    float v[4];
    float ss = 0.f;
#pragma unroll
    for (int i = 0; i < 4; i++) { v[i] = x[t + 512 * i]; ss += v[i] * v[i]; }
    ss = block_sum(ss);
    float inv = rsqrtf(ss / (float)DMODEL + EPSF);
#pragma unroll
    for (int i = 0; i < 4; i++) out[t + 512 * i] = v[i] * inv * w[t + 512 * i];
}

// h += rms(sum partials)*w
template <int NSPLIT>
__global__ void k_rms_add(const float* __restrict__ part, const float* __restrict__ w,
                          float* __restrict__ h) {
    int t = threadIdx.x;
    float v[4];
    float ss = 0.f;
#pragma unroll
    for (int i = 0; i < 4; i++) {
        int j = t + 512 * i;
        float r = 0.f;
#pragma unroll
        for (int s = 0; s < NSPLIT; s++) r += part[s * DMODEL + j];
        v[i] = r;
        ss += r * r;
    }
    ss = block_sum(ss);
    float inv = rsqrtf(ss / (float)DMODEL + EPSF);
#pragma unroll
    for (int i = 0; i < 4; i++) h[t + 512 * i] += v[i] * inv * w[t + 512 * i];
}

// h += rms(sum partials)*w1 ; hn = rms(h_new)*w2
template <int NSPLIT>
__global__ void k_rms_add_norm(const float* __restrict__ part, const float* __restrict__ w1,
                               float* __restrict__ h, const float* __restrict__ w2,
                               float* __restrict__ hn) {
    int t = threadIdx.x;
    float v[4], hv[4];
    float ss = 0.f;
#pragma unroll
    for (int i = 0; i < 4; i++) {
        int j = t + 512 * i;
        float r = 0.f;
#pragma unroll
        for (int s = 0; s < NSPLIT; s++) r += part[s * DMODEL + j];
        v[i] = r;
        ss += r * r;
    }
    ss = block_sum(ss);
    float inv = rsqrtf(ss / (float)DMODEL + EPSF);
    float ss2 = 0.f;
#pragma unroll
    for (int i = 0; i < 4; i++) {
        hv[i] = h[t + 512 * i] + v[i] * inv * w1[t + 512 * i];
        ss2 += hv[i] * hv[i];
    }
    ss2 = block_sum(ss2);
    float inv2 = rsqrtf(ss2 / (float)DMODEL + EPSF);
#pragma unroll
    for (int i = 0; i < 4; i++) {
        h[t + 512 * i] = hv[i];
        hn[t + 512 * i] = hv[i] * inv2 * w2[t + 512 * i];
    }
}

// h = (h + rms(raw)*w) * sc[0] ; hn = rms(h_new)*w2   (fused tail + next-layer input norm)
__global__ void k_rms_add_scale_norm(const float* __restrict__ raw, const float* __restrict__ w,
                                     const float* __restrict__ sc, float* __restrict__ h,
                                     const float* __restrict__ w2, float* __restrict__ hn) {
    int t = threadIdx.x;
    float v[4], hv[4];
    float ss = 0.f;
#pragma unroll
    for (int i = 0; i < 4; i++) { v[i] = raw[t + 512 * i]; ss += v[i] * v[i]; }
    ss = block_sum(ss);
    float inv = rsqrtf(ss / (float)DMODEL + EPSF);
    float s = sc[0];
    float ss2 = 0.f;
#pragma unroll
    for (int i = 0; i < 4; i++) {
        hv[i] = (h[t + 512 * i] + v[i] * inv * w[t + 512 * i]) * s;
        ss2 += hv[i] * hv[i];
    }
    ss2 = block_sum(ss2);
    float inv2 = rsqrtf(ss2 / (float)DMODEL + EPSF);
#pragma unroll
    for (int i = 0; i < 4; i++) {
        h[t + 512 * i] = hv[i];
        hn[t + 512 * i] = hv[i] * inv2 * w2[t + 512 * i];
    }
}

// K-split GEMV, persistent one-wave grid, front-batched register loads.
// work unit u: (grp = u % NGRP) row-group of 8, (c = u / NGRP) k-chunk.
// ypart[c * NGRP*8 + row] = W[row, c*KCH:(c+1)*KCH] . x[c*KCH:...]
template <int DIM, int NSPLIT, int NGRP>
__global__ void k_gemv_split(const float* __restrict__ W, const float* __restrict__ x,
                             float* __restrict__ ypart) {
    constexpr int KCH = DIM / NSPLIT;
    constexpr int NB = KCH / 128;       // float4 loads per lane per unit
    constexpr int NUNITS = NGRP * NSPLIT;
    constexpr int ROWS = NGRP * 8;
    __shared__ float4 xs[KCH / 4];
    int t = threadIdx.x;
    int warp = t >> 5, lane = t & 31;
    for (int u = blockIdx.x; u < NUNITS; u += gridDim.x) {
        int grp = u % NGRP;
        int c = u / NGRP;
        int row = grp * 8 + warp;
        const float4* wr = (const float4*)(W + (size_t)row * DIM + c * KCH);
        float4 a[NB];
#pragma unroll
        for (int i = 0; i < NB; i++) a[i] = __ldcs(wr + lane + 32 * i);
        __syncthreads();   // previous unit's xs consumers done
        const float4* xp = (const float4*)(x + c * KCH);
        for (int i = t; i < KCH / 4; i += 256) xs[i] = xp[i];
        __syncthreads();
        float acc = 0.f;
#pragma unroll
        for (int i = 0; i < NB; i++) acc += dot4(a[i], xs[lane + 32 * i]);
        acc = warp_sum(acc);
        if (lane == 0) ypart[c * ROWS + row] = acc;
    }
}

// fused q/k/v projection, split-4, persistent grid. rows: q 0..2047, k 2048..2559, v 2560..3071
__global__ void k_gemv_qkv_split(const float* __restrict__ Wq, const float* __restrict__ Wk,
                                 const float* __restrict__ Wv, const float* __restrict__ x,
                                 float* __restrict__ ypart) {
    constexpr int KCH = DMODEL / 4;     // 512
    constexpr int NB = KCH / 128;       // 4
    constexpr int NGRP = 384;
    constexpr int NUNITS = NGRP * 4;    // 1536
    __shared__ float4 xs[KCH / 4];
    int t = threadIdx.x;
    int warp = t >> 5, lane = t & 31;
    for (int u = blockIdx.x; u < NUNITS; u += gridDim.x) {
        int grp = u % NGRP;
        int c = u / NGRP;
        int row = grp * 8 + warp;
        const float* W;
        int r;
        if (row < 2048) { W = Wq; r = row; }
        else if (row < 2560) { W = Wk; r = row - 2048; }
        else { W = Wv; r = row - 2560; }
        const float4* wr = (const float4*)(W + (size_t)r * DMODEL + c * KCH);
        float4 a[NB];
#pragma unroll
        for (int i = 0; i < NB; i++) a[i] = __ldcs(wr + lane + 32 * i);
        __syncthreads();
        const float4* xp = (const float4*)(x + c * KCH);
        for (int i = t; i < KCH / 4; i += 256) xs[i] = xp[i];
        __syncthreads();
        float acc = 0.f;
#pragma unroll
        for (int i = 0; i < NB; i++) acc += dot4(a[i], xs[lane + 32 * i]);
        acc = warp_sum(acc);
        if (lane == 0) ypart[c * 3072 + row] = acc;
    }
}

// fused gate/up GEMV, persistent grid, full-K rows, batched loads (8 in flight).
__global__ void k_gemv_gateup(const float* __restrict__ Wg, const float* __restrict__ Wu,
                              const float* __restrict__ x, float* __restrict__ act) {
    __shared__ float4 xs[DMODEL / 4];
    int t = threadIdx.x;
    for (int i = t; i < DMODEL / 4; i += 256) xs[i] = ((const float4*)x)[i];
    __syncthreads();
    int warp = t >> 5, lane = t & 31;
    for (int u = blockIdx.x; u < FFDIM / 8; u += gridDim.x) {
        int row = u * 8 + warp;
        const float4* wg = (const float4*)(Wg + (size_t)row * DMODEL);
        const float4* wu = (const float4*)(Wu + (size_t)row * DMODEL);
        float sg = 0.f, su = 0.f;
#pragma unroll
        for (int kb = 0; kb < 4; kb++) {
            float4 a[4], c4[4];
#pragma unroll
            for (int i = 0; i < 4; i++) a[i] = __ldcs(wg + lane + 32 * (kb * 4 + i));
#pragma unroll
            for (int i = 0; i < 4; i++) c4[i] = __ldcs(wu + lane + 32 * (kb * 4 + i));
#pragma unroll
            for (int i = 0; i < 4; i++) {
                float4 b = xs[lane + 32 * (kb * 4 + i)];
                sg += dot4(a[i], b);
                su += dot4(c4[i], b);
            }
        }
        sg = warp_sum(sg);
        su = warp_sum(su);
        if (lane == 0) act[row] = gelu_t(sg) * su;
    }
}

// per-layer gate: block per row (256 blocks), y[r] = gelu(W[r].h) * pl[r]
__global__ void k_plg_rowblock(const float* __restrict__ W, const float* __restrict__ x,
                               const float* __restrict__ pl, float* __restrict__ y) {
    int r = blockIdx.x, t = threadIdx.x;
    const float4* wr = (const float4*)(W + (size_t)r * DMODEL);
    const float4* xp = (const float4*)x;
    float4 a0 = __ldcs(wr + t), a1 = __ldcs(wr + t + 256);
    float s = dot4(a0, xp[t]) + dot4(a1, xp[t + 256]);
    s = block_sum(s);
    if (t == 0) y[r] = gelu_t(s) * pl[r];
}

// small gemv (plp): warp per row, 8 rows/block
template <int DIM>
__global__ void k_gemv(const float* __restrict__ W, const float* __restrict__ x,
                       float* __restrict__ y) {
    __shared__ float4 xs[DIM / 4];
    int t = threadIdx.x;
    for (int i = t; i < DIM / 4; i += 256) xs[i] = ((const float4*)x)[i];
    __syncthreads();
    int warp = t >> 5, lane = t & 31;
    int row = blockIdx.x * 8 + warp;
    const float4* wr = (const float4*)(W + (size_t)row * DIM);
    float s = 0.f;
#pragma unroll
    for (int k = 0; k < DIM / 128; k++)
        s += dot4(__ldcs(wr + lane + 32 * k), xs[lane + 32 * k]);
    s = warp_sum(s);
    if (lane == 0) y[row] = s;
}

// per-head rms norm + (qn/kn) scale + rope; input = 4-way partial sums
__global__ void k_hnr(const float* __restrict__ qp, const float* __restrict__ qn,
                      const float* __restrict__ kn, const float* __restrict__ cosp,
                      const float* __restrict__ sinp, float* __restrict__ q,
                      float* __restrict__ knew, float* __restrict__ vnew,
                      float* __restrict__ outK_l, float* __restrict__ outV_l) {
    int b = blockIdx.x, t = threadIdx.x;
    int j = b * 256 + t;
    float x = qp[j] + qp[3072 + j] + qp[6144 + j] + qp[9216 + j];
    float ss = block_sum(x * x);
    float inv = rsqrtf(ss / (float)HDIM + EPSF);
    __shared__ float sv[256];
    float val;
    if (b < 8) val = x * inv * qn[t];
    else if (b < 10) val = x * inv * kn[t];
    else val = x * inv;
    sv[t] = val;
    __syncthreads();
    float out;
    if (b < 10) {
        float other = (t < 128) ? -sv[t + 128] : sv[t - 128];
        out = val * cosp[t] + other * sinp[t];
    } else {
        out = val;
    }
    if (b < 8) {
        q[b * 256 + t] = out;
    } else if (b < 10) {
        int kv = b - 8;
        knew[kv * 256 + t] = out;
        outK_l[((size_t)kv * SEQ + POS) * HDIM + t] = out;
    } else {
        int kv = b - 10;
        vnew[kv * 256 + t] = out;
        outV_l[((size_t)kv * SEQ + POS) * HDIM + t] = out;
    }
}

// attention scores: grid (8 heads, 33 chunks of 64), 256 threads (8 warps)
__global__ void k_scores(const float* __restrict__ q, const float* __restrict__ Kl,
                         const float* __restrict__ knew, float* __restrict__ scores) {
    int h = blockIdx.x, c = blockIdx.y, t = threadIdx.x;
    int kv = h >> 2;
    __shared__ float4 qs[64];
    if (t < 64) qs[t] = ((const float4*)(q + h * 256))[t];
    __syncthreads();
    int warp = t >> 5, lane = t & 31;
    const float* Kbase = Kl + (size_t)kv * SEQ * HDIM;
    const float* knv = knew + kv * HDIM;
    int s0 = c * 64;
#pragma unroll
    for (int i = 0; i < 8; i++) {
        int s = s0 + i * 8 + warp;
        if (s <= POS) {
            const float4* kr = (s == POS) ? (const float4*)knv
                                          : (const float4*)(Kbase + (size_t)s * HDIM);
            float4 a0 = __ldcs(kr + lane), a1 = __ldcs(kr + lane + 32);
            float acc = dot4(a0, qs[lane]) + dot4(a1, qs[lane + 32]);
            acc = warp_sum(acc);
            if (lane == 0) scores[h * SSTR + s] = acc;
        }
    }
}

// softmax per head over NS positions; also zeroes attn accumulator
__global__ void k_softmax(float* __restrict__ scores, float* __restrict__ attn) {
    int h = blockIdx.x, t = threadIdx.x;
    __shared__ float sh[NS];
    float m = -3.0e38f;
    for (int s = t; s < NS; s += 256) {
        float v = scores[h * SSTR + s];
        sh[s] = v;
        m = fmaxf(m, v);
    }
    m = block_max(m);
    float sum = 0.f;
    for (int s = t; s < NS; s += 256) {
        float e = __expf(sh[s] - m);
        sh[s] = e;
        sum += e;
    }
    sum = block_sum(sum);
    float invz = 1.f / sum;
    for (int s = t; s < NS; s += 256) scores[h * SSTR + s] = sh[s] * invz;
    attn[h * HDIM + t] = 0.f;
}

// attn[h,d] += sum over chunk of p[s]*V[s,d]; grid (8, 33), 256 threads (= d)
__global__ void k_attnv(const float* __restrict__ scores, const float* __restrict__ Vl,
                        const float* __restrict__ vnew, float* __restrict__ attn) {
    int h = blockIdx.x, c = blockIdx.y, t = threadIdx.x;
    int kv = h >> 2;
    __shared__ float ps[64];
    int s0 = c * 64;
    if (t < 64) {
        int s = s0 + t;
        ps[t] = (s <= POS) ? scores[h * SSTR + s] : 0.f;
    }
    __syncthreads();
    const float* Vbase = Vl + (size_t)kv * SEQ * HDIM;
    const float* vnv = vnew + kv * HDIM;
    float acc = 0.f;
#pragma unroll 4
    for (int i = 0; i < 64; i++) {
        int s = s0 + i;
        const float* vr = (s == POS) ? vnv : (Vbase + (size_t)s * HDIM);
        acc += ps[i] * vr[t];
    }
    atomicAdd(&attn[h * HDIM + t], acc);
}

// ---------------- host launcher ----------------
extern "C" void kernel_launch(void* const* d_in, const int* in_sizes, int n_in,
                              void* d_out, int out_size) {
    const float* hs    = (const float*)d_in[0];
    const float* pls   = (const float*)d_in[3];
    const float* cos_s = (const float*)d_in[4];
    const float* sin_s = (const float*)d_in[5];
    const float* cos_f = (const float*)d_in[6];
    const float* sin_f = (const float*)d_in[7];
    const float* K_in  = (const float*)d_in[8];
    const float* V_in  = (const float*)d_in[9];
    const float* Wq    = (const float*)d_in[10];
    const float* Wk    = (const float*)d_in[11];
    const float* Wv    = (const float*)d_in[12];
    const float* Wo    = (const float*)d_in[13];
    const float* qn    = (const float*)d_in[14];
    const float* kn    = (const float*)d_in[15];
    const float* ln_in   = (const float*)d_in[16];
    const float* ln_pa   = (const float*)d_in[17];
    const float* ln_pre  = (const float*)d_in[18];
    const float* ln_post = (const float*)d_in[19];
    const float* ln_pl   = (const float*)d_in[20];
    const float* Wg    = (const float*)d_in[21];
    const float* Wu    = (const float*)d_in[22];
    const float* Wd    = (const float*)d_in[23];
    const float* Wplg  = (const float*)d_in[24];
    const float* Wplp  = (const float*)d_in[25];
    const float* lsc   = (const float*)d_in[26];

    float* out = (float*)d_out;
    const size_t kvsz = (size_t)NLAYER * NKV * SEQ * HDIM;  // 16,777,216
    float* outK = out + DMODEL;
    float* outV = outK + kvsz;

    float* sb = nullptr;
    cudaGetSymbolAddress((void**)&sb, g_scratch);
    float* b_h    = sb + OFF_H;
    float* b_hn   = sb + OFF_HN;
    float* b_q    = sb + OFF_Q;
    float* b_knew = sb + OFF_KNEW;
    float* b_vnew = sb + OFF_VNEW;
    float* b_attn = sb + OFF_ATTN;
    float* b_act  = sb + OFF_ACT;
    float* b_g2   = sb + OFF_G2;
    float* b_sc   = sb + OFF_SC;
    float* b_part = sb + OFF_PART;

    // bulk KV copy (old cache -> output); updated rows overwritten per-layer below
    k_copy_kv<<<1184, 256>>>((const float4*)K_in, (const float4*)V_in,
                             (float4*)outK, (float4*)outV, (int)(kvsz / 4));
    // h = hidden_states ; hn = rms(h)*ln_in[0]
    k_copy<<<8, 256>>>(hs, b_h, DMODEL);
    k_rms_scale<<<1, 512>>>(b_h, ln_in, b_hn);

    for (int l = 0; l < NLAYER; l++) {
        const float* Wq_l = Wq + (size_t)l * 2048 * 2048;
        const float* Wk_l = Wk + (size_t)l * 512 * 2048;
        const float* Wv_l = Wv + (size_t)l * 512 * 2048;
        const float* Wo_l = Wo + (size_t)l * 2048 * 2048;
        const float* Wg_l = Wg + (size_t)l * 8192 * 2048;
        const float* Wu_l = Wu + (size_t)l * 8192 * 2048;
        const float* Wd_l = Wd + (size_t)l * 2048 * 8192;
        const float* Wplg_l = Wplg + (size_t)l * 256 * 2048;
        const float* Wplp_l = Wplp + (size_t)l * 2048 * 256;
        const float* K_l = K_in + (size_t)l * NKV * SEQ * HDIM;
        const float* V_l = V_in + (size_t)l * NKV * SEQ * HDIM;
        float* outK_l = outK + (size_t)l * NKV * SEQ * HDIM;
        float* outV_l = outV + (size_t)l * NKV * SEQ * HDIM;
        bool full = ((l + 1) % 5) == 0;
        const float* cp = full ? cos_f : cos_s;
        const float* sp = full ? sin_f : sin_s;
        const float* ln_in_next = ln_in + ((l + 1 < NLAYER) ? (l + 1) : 0) * DMODEL;

        // attention block
        k_gemv_qkv_split<<<NBLK, 256>>>(Wq_l, Wk_l, Wv_l, b_hn, b_part);
        k_hnr<<<12, 256>>>(b_part, qn + l * HDIM, kn + l * HDIM, cp, sp,
                           b_q, b_knew, b_vnew, outK_l, outV_l);
        k_scores<<<dim3(8, 33), 256>>>(b_q, K_l, b_knew, b_sc);
        k_softmax<<<8, 256>>>(b_sc, b_attn);
        k_attnv<<<dim3(8, 33), 256>>>(b_sc, V_l, b_vnew, b_attn);
        k_gemv_split<2048, 4, 256><<<NBLK, 256>>>(Wo_l, b_attn, b_part);
        k_rms_add_norm<4><<<1, 512>>>(b_part, ln_pa + l * DMODEL, b_h,
                                      ln_pre + l * DMODEL, b_hn);
        // MLP block
        k_gemv_gateup<<<NBLK, 256>>>(Wg_l, Wu_l, b_hn, b_act);
        k_gemv_split<8192, 8, 256><<<NBLK, 256>>>(Wd_l, b_act, b_part);
        k_rms_add<8><<<1, 512>>>(b_part, ln_post + l * DMODEL, b_h);
        // per-layer block
        k_plg_rowblock<<<256, 256>>>(Wplg_l, b_h, pls + l * PLDIM, b_g2);
        k_gemv<256><<<256, 256>>>(Wplp_l, b_g2, b_part);
        k_rms_add_scale_norm<<<1, 512>>>(b_part, ln_pl + l * DMODEL, lsc + l,
                                         b_h, ln_in_next, b_hn);
    }

    // final hidden state
    k_copy<<<8, 256>>>(b_h, out, DMODEL);
}

// round 4
// speedup vs baseline: 1.2713x; 1.0544x over previous
#include <cuda_runtime.h>
#include <cstddef>

#define NLAYER 8
#define DMODEL 2048
#define NHEAD 8
#define NKV 2
#define HDIM 256
#define SEQ 4096
#define FFDIM 8192
#define PLDIM 256
#define POS 2048
#define NS 2049          // valid attention positions (0..POS)
#define SSTR 2080        // padded score row stride
#define EPSF 1e-6f

// ---------------- scratch (device global, no allocation) ----------------
#define OFF_H     0
#define OFF_HN    2048
#define OFF_Q     4096
#define OFF_KNEW  6144
#define OFF_VNEW  6656
#define OFF_ATTN  7168
#define OFF_ACT   9216
#define OFF_G2    17408
#define OFF_SC    17664              // 8*2080 = 16640
#define OFF_PART  34304              // up to 16384 floats of partials
__device__ __align__(16) float g_scratch[34304 + 16384];

// ---------------- helpers ----------------
__device__ __forceinline__ float warp_sum(float v) {
#pragma unroll
    for (int o = 16; o; o >>= 1) v += __shfl_xor_sync(0xffffffffu, v, o);
    return v;
}
__device__ __forceinline__ float warp_max(float v) {
#pragma unroll
    for (int o = 16; o; o >>= 1) v = fmaxf(v, __shfl_xor_sync(0xffffffffu, v, o));
    return v;
}
__device__ __forceinline__ float block_sum(float v) {
    __shared__ float red[16];
    __shared__ float tot;
    int t = threadIdx.x, nw = (int)(blockDim.x >> 5);
    __syncthreads();
    v = warp_sum(v);
    if ((t & 31) == 0) red[t >> 5] = v;
    __syncthreads();
    if (t < 32) {
        float s = (t < nw) ? red[t] : 0.f;
        s = warp_sum(s);
        if (t == 0) tot = s;
    }
    __syncthreads();
    return tot;
}
__device__ __forceinline__ float block_max(float v) {
    __shared__ float red[16];
    __shared__ float tot;
    int t = threadIdx.x, nw = (int)(blockDim.x >> 5);
    __syncthreads();
    v = warp_max(v);
    if ((t & 31) == 0) red[t >> 5] = v;
    __syncthreads();
    if (t < 32) {
        float s = (t < nw) ? red[t] : -3.0e38f;
        s = warp_max(s);
        if (t == 0) tot = s;
    }
    __syncthreads();
    return tot;
}
__device__ __forceinline__ float gelu_t(float x) {
    float x3 = x * x * x;
    return 0.5f * x * (1.f + tanhf(0.7978845608028654f * (x + 0.044715f * x3)));
}
__device__ __forceinline__ float dot4(float4 a, float4 b) {
    return a.x * b.x + a.y * b.y + a.z * b.z + a.w * b.w;
}

// ---------------- kernels ----------------

// big KV copy, 2x ILP per array
__global__ void k_copy_kv(const float4* __restrict__ a, const float4* __restrict__ b,
                          float4* __restrict__ oa, float4* __restrict__ ob, int n4) {
    int i = (blockIdx.x * blockDim.x + threadIdx.x) * 2;
    int stride = gridDim.x * blockDim.x * 2;
    for (; i < n4; i += stride) {
        float4 a0 = a[i], a1 = a[i + 1];
        float4 b0 = b[i], b1 = b[i + 1];
        oa[i] = a0; oa[i + 1] = a1;
        ob[i] = b0; ob[i + 1] = b1;
    }
}

__global__ void k_copy(const float* __restrict__ src, float* __restrict__ dst, int n) {
    int i = blockIdx.x * blockDim.x + threadIdx.x;
    if (i < n) dst[i] = src[i];
}

// out = rms(x)*w   (1 block, 512 threads)
__global__ void k_rms_scale(const float* __restrict__ x, const float* __restrict__ w,
                            float* __restrict__ out) {
    int t = threadIdx.x;
    float v[4];
    float ss = 0.f;
#pragma unroll
    for (int i = 0; i < 4; i++) { v[i] = x[t + 512 * i]; ss += v[i] * v[i]; }
    ss = block_sum(ss);
    float inv = rsqrtf(ss / (float)DMODEL + EPSF);
#pragma unroll
    for (int i = 0; i < 4; i++) out[t + 512 * i] = v[i] * inv * w[t + 512 * i];
}

// h += rms(sum partials)*w
template <int NSPLIT>
__global__ void k_rms_add(const float* __restrict__ part, const float* __restrict__ w,
                          float* __restrict__ h) {
    int t = threadIdx.x;
    float v[4];
    float ss = 0.f;
#pragma unroll
    for (int i = 0; i < 4; i++) {
        int j = t + 512 * i;
        float r = 0.f;
#pragma unroll
        for (int s = 0; s < NSPLIT; s++) r += part[s * DMODEL + j];
        v[i] = r;
        ss += r * r;
    }
    ss = block_sum(ss);
    float inv = rsqrtf(ss / (float)DMODEL + EPSF);
#pragma unroll
    for (int i = 0; i < 4; i++) h[t + 512 * i] += v[i] * inv * w[t + 512 * i];
}

// h += rms(sum partials)*w1 ; hn = rms(h_new)*w2
template <int NSPLIT>
__global__ void k_rms_add_norm(const float* __restrict__ part, const float* __restrict__ w1,
                               float* __restrict__ h, const float* __restrict__ w2,
                               float* __restrict__ hn) {
    int t = threadIdx.x;
    float v[4], hv[4];
    float ss = 0.f;
#pragma unroll
    for (int i = 0; i < 4; i++) {
        int j = t + 512 * i;
        float r = 0.f;
#pragma unroll
        for (int s = 0; s < NSPLIT; s++) r += part[s * DMODEL + j];
        v[i] = r;
        ss += r * r;
    }
    ss = block_sum(ss);
    float inv = rsqrtf(ss / (float)DMODEL + EPSF);
    float ss2 = 0.f;
#pragma unroll
    for (int i = 0; i < 4; i++) {
        hv[i] = h[t + 512 * i] + v[i] * inv * w1[t + 512 * i];
        ss2 += hv[i] * hv[i];
    }
    ss2 = block_sum(ss2);
    float inv2 = rsqrtf(ss2 / (float)DMODEL + EPSF);
#pragma unroll
    for (int i = 0; i < 4; i++) {
        h[t + 512 * i] = hv[i];
        hn[t + 512 * i] = hv[i] * inv2 * w2[t + 512 * i];
    }
}

// h = (h + rms(raw)*w) * sc[0] ; hn = rms(h_new)*w2
__global__ void k_rms_add_scale_norm(const float* __restrict__ raw, const float* __restrict__ w,
                                     const float* __restrict__ sc, float* __restrict__ h,
                                     const float* __restrict__ w2, float* __restrict__ hn) {
    int t = threadIdx.x;
    float v[4], hv[4];
    float ss = 0.f;
#pragma unroll
    for (int i = 0; i < 4; i++) { v[i] = raw[t + 512 * i]; ss += v[i] * v[i]; }
    ss = block_sum(ss);
    float inv = rsqrtf(ss / (float)DMODEL + EPSF);
    float s = sc[0];
    float ss2 = 0.f;
#pragma unroll
    for (int i = 0; i < 4; i++) {
        hv[i] = (h[t + 512 * i] + v[i] * inv * w[t + 512 * i]) * s;
        ss2 += hv[i] * hv[i];
    }
    ss2 = block_sum(ss2);
    float inv2 = rsqrtf(ss2 / (float)DMODEL + EPSF);
#pragma unroll
    for (int i = 0; i < 4; i++) {
        h[t + 512 * i] = hv[i];
        hn[t + 512 * i] = hv[i] * inv2 * w2[t + 512 * i];
    }
}

// GEMV, one block = one (row-group, k-chunk) unit. KCH = 1024 floats.
// Warp front-issues all 8 LDG.128 for its chunk, overlapping the xs smem fill.
// ypart[c * ROWS + row] = W[row, c*1024 : (c+1)*1024] . x[c*1024 : ...]
template <int ROWS, int DIM>
__global__ void k_gemv_b8(const float* __restrict__ W, const float* __restrict__ x,
                          float* __restrict__ ypart) {
    constexpr int KCH = 1024;
    constexpr int NGRP = ROWS / 8;
    __shared__ float4 xs[KCH / 4];          // 4 KB
    int t = threadIdx.x, warp = t >> 5, lane = t & 31;
    int grp = blockIdx.x % NGRP;
    int c = blockIdx.x / NGRP;
    int row = grp * 8 + warp;
    const float4* wr = (const float4*)(W + (size_t)row * DIM + c * KCH);
    float4 a[8];
#pragma unroll
    for (int i = 0; i < 8; i++) a[i] = __ldcs(wr + lane + 32 * i);
    xs[t] = ((const float4*)(x + c * KCH))[t];
    __syncthreads();
    float acc = 0.f;
#pragma unroll
    for (int i = 0; i < 8; i++) acc += dot4(a[i], xs[lane + 32 * i]);
    acc = warp_sum(acc);
    if (lane == 0) ypart[c * ROWS + row] = acc;
}

// fused q/k/v projection, split-2 (KCH=1024), grid 768
__global__ void k_gemv_qkv_b8(const float* __restrict__ Wq, const float* __restrict__ Wk,
                              const float* __restrict__ Wv, const float* __restrict__ x,
                              float* __restrict__ ypart) {
    constexpr int KCH = 1024;
    __shared__ float4 xs[KCH / 4];
    int t = threadIdx.x, warp = t >> 5, lane = t & 31;
    int grp = blockIdx.x % 384;
    int c = blockIdx.x / 384;
    int row = grp * 8 + warp;
    const float* W;
    int r;
    if (row < 2048) { W = Wq; r = row; }
    else if (row < 2560) { W = Wk; r = row - 2048; }
    else { W = Wv; r = row - 2560; }
    const float4* wr = (const float4*)(W + (size_t)r * DMODEL + c * KCH);
    float4 a[8];
#pragma unroll
    for (int i = 0; i < 8; i++) a[i] = __ldcs(wr + lane + 32 * i);
    xs[t] = ((const float4*)(x + c * KCH))[t];
    __syncthreads();
    float acc = 0.f;
#pragma unroll
    for (int i = 0; i < 8; i++) acc += dot4(a[i], xs[lane + 32 * i]);
    acc = warp_sum(acc);
    if (lane == 0) ypart[c * 3072 + row] = acc;
}

// fused gate/up GEMV, full-K rows, 4-phase pipelined loads (8-16 LDG.128 in flight)
__global__ void k_gemv_gateup(const float* __restrict__ Wg, const float* __restrict__ Wu,
                              const float* __restrict__ x, float* __restrict__ act) {
    __shared__ float4 xs[DMODEL / 4];       // 8 KB
    int t = threadIdx.x, warp = t >> 5, lane = t & 31;
    int row = blockIdx.x * 8 + warp;
    const float4* wg = (const float4*)(Wg + (size_t)row * DMODEL);
    const float4* wu = (const float4*)(Wu + (size_t)row * DMODEL);
    float4 a[8], c4[8];
    // phase 0: issue gate-half0 + up-half0 (16 in flight), fill xs meanwhile
#pragma unroll
    for (int i = 0; i < 8; i++) a[i] = __ldcs(wg + lane + 32 * i);
#pragma unroll
    for (int i = 0; i < 8; i++) c4[i] = __ldcs(wu + lane + 32 * i);
    xs[t] = ((const float4*)x)[t];
    xs[t + 256] = ((const float4*)x)[t + 256];
    __syncthreads();
    float sg = 0.f, su = 0.f;
    // consume gate-half0, then refill a with gate-half1 (keeps loads in flight)
#pragma unroll
    for (int i = 0; i < 8; i++) sg += dot4(a[i], xs[lane + 32 * i]);
#pragma unroll
    for (int i = 0; i < 8; i++) a[i] = __ldcs(wg + 256 + lane + 32 * i);
    // consume up-half0, refill c4 with up-half1
#pragma unroll
    for (int i = 0; i < 8; i++) su += dot4(c4[i], xs[lane + 32 * i]);
#pragma unroll
    for (int i = 0; i < 8; i++) c4[i] = __ldcs(wu + 256 + lane + 32 * i);
    // consume second halves
#pragma unroll
    for (int i = 0; i < 8; i++) sg += dot4(a[i], xs[256 + lane + 32 * i]);
#pragma unroll
    for (int i = 0; i < 8; i++) su += dot4(c4[i], xs[256 + lane + 32 * i]);
    sg = warp_sum(sg);
    su = warp_sum(su);
    if (lane == 0) act[row] = gelu_t(sg) * su;
}

// per-layer gate: block per row (256 blocks), y[r] = gelu(W[r].h) * pl[r]
__global__ void k_plg_rowblock(const float* __restrict__ W, const float* __restrict__ x,
                               const float* __restrict__ pl, float* __restrict__ y) {
    int r = blockIdx.x, t = threadIdx.x;
    const float4* wr = (const float4*)(W + (size_t)r * DMODEL);
    const float4* xp = (const float4*)x;
    float4 a0 = __ldcs(wr + t), a1 = __ldcs(wr + t + 256);
    float s = dot4(a0, xp[t]) + dot4(a1, xp[t + 256]);
    s = block_sum(s);
    if (t == 0) y[r] = gelu_t(s) * pl[r];
}

// small gemv (plp): warp per row, 8 rows/block
template <int DIM>
__global__ void k_gemv(const float* __restrict__ W, const float* __restrict__ x,
                       float* __restrict__ y) {
    __shared__ float4 xs[DIM / 4];
    int t = threadIdx.x;
    for (int i = t; i < DIM / 4; i += 256) xs[i] = ((const float4*)x)[i];
    __syncthreads();
    int warp = t >> 5, lane = t & 31;
    int row = blockIdx.x * 8 + warp;
    const float4* wr = (const float4*)(W + (size_t)row * DIM);
    float s = 0.f;
#pragma unroll
    for (int k = 0; k < DIM / 128; k++)
        s += dot4(__ldcs(wr + lane + 32 * k), xs[lane + 32 * k]);
    s = warp_sum(s);
    if (lane == 0) y[row] = s;
}

// per-head rms norm + (qn/kn) scale + rope; input = 2-way partial sums
__global__ void k_hnr(const float* __restrict__ qp, const float* __restrict__ qn,
                      const float* __restrict__ kn, const float* __restrict__ cosp,
                      const float* __restrict__ sinp, float* __restrict__ q,
                      float* __restrict__ knew, float* __restrict__ vnew,
                      float* __restrict__ outK_l, float* __restrict__ outV_l) {
    int b = blockIdx.x, t = threadIdx.x;
    int j = b * 256 + t;
    float x = qp[j] + qp[3072 + j];
    float ss = block_sum(x * x);
    float inv = rsqrtf(ss / (float)HDIM + EPSF);
    __shared__ float sv[256];
    float val;
    if (b < 8) val = x * inv * qn[t];
    else if (b < 10) val = x * inv * kn[t];
    else val = x * inv;
    sv[t] = val;
    __syncthreads();
    float out;
    if (b < 10) {
        float other = (t < 128) ? -sv[t + 128] : sv[t - 128];
        out = val * cosp[t] + other * sinp[t];
    } else {
        out = val;
    }
    if (b < 8) {
        q[b * 256 + t] = out;
    } else if (b < 10) {
        int kv = b - 8;
        knew[kv * 256 + t] = out;
        outK_l[((size_t)kv * SEQ + POS) * HDIM + t] = out;
    } else {
        int kv = b - 10;
        vnew[kv * 256 + t] = out;
        outV_l[((size_t)kv * SEQ + POS) * HDIM + t] = out;
    }
}

// attention scores: grid (8 heads, 33 chunks of 64), 256 threads (8 warps)
__global__ void k_scores(const float* __restrict__ q, const float* __restrict__ Kl,
                         const float* __restrict__ knew, float* __restrict__ scores) {
    int h = blockIdx.x, c = blockIdx.y, t = threadIdx.x;
    int kv = h >> 2;
    __shared__ float4 qs[64];
    if (t < 64) qs[t] = ((const float4*)(q + h * 256))[t];
    __syncthreads();
    int warp = t >> 5, lane = t & 31;
    const float* Kbase = Kl + (size_t)kv * SEQ * HDIM;
    const float* knv = knew + kv * HDIM;
    int s0 = c * 64;
#pragma unroll
    for (int i = 0; i < 8; i++) {
        int s = s0 + i * 8 + warp;
        if (s <= POS) {
            const float4* kr = (s == POS) ? (const float4*)knv
                                          : (const float4*)(Kbase + (size_t)s * HDIM);
            float4 a0 = __ldcs(kr + lane), a1 = __ldcs(kr + lane + 32);
            float acc = dot4(a0, qs[lane]) + dot4(a1, qs[lane + 32]);
            acc = warp_sum(acc);
            if (lane == 0) scores[h * SSTR + s] = acc;
        }
    }
}

// softmax per head over NS positions; also zeroes attn accumulator
__global__ void k_softmax(float* __restrict__ scores, float* __restrict__ attn) {
    int h = blockIdx.x, t = threadIdx.x;
    __shared__ float sh[NS];
    float m = -3.0e38f;
    for (int s = t; s < NS; s += 256) {
        float v = scores[h * SSTR + s];
        sh[s] = v;
        m = fmaxf(m, v);
    }
    m = block_max(m);
    float sum = 0.f;
    for (int s = t; s < NS; s += 256) {
        float e = __expf(sh[s] - m);
        sh[s] = e;
        sum += e;
    }
    sum = block_sum(sum);
    float invz = 1.f / sum;
    for (int s = t; s < NS; s += 256) scores[h * SSTR + s] = sh[s] * invz;
    attn[h * HDIM + t] = 0.f;
}

// attn[h,d] += sum over chunk of p[s]*V[s,d]; grid (8, 33), 256 threads (= d)
__global__ void k_attnv(const float* __restrict__ scores, const float* __restrict__ Vl,
                        const float* __restrict__ vnew, float* __restrict__ attn) {
    int h = blockIdx.x, c = blockIdx.y, t = threadIdx.x;
    int kv = h >> 2;
    __shared__ float ps[64];
    int s0 = c * 64;
    if (t < 64) {
        int s = s0 + t;
        ps[t] = (s <= POS) ? scores[h * SSTR + s] : 0.f;
    }
    __syncthreads();
    const float* Vbase = Vl + (size_t)kv * SEQ * HDIM;
    const float* vnv = vnew + kv * HDIM;
    float acc = 0.f;
#pragma unroll 4
    for (int i = 0; i < 64; i++) {
        int s = s0 + i;
        const float* vr = (s == POS) ? vnv : (Vbase + (size_t)s * HDIM);
        acc += ps[i] * vr[t];
    }
    atomicAdd(&attn[h * HDIM + t], acc);
}

// ---------------- host launcher ----------------
extern "C" void kernel_launch(void* const* d_in, const int* in_sizes, int n_in,
                              void* d_out, int out_size) {
    const float* hs    = (const float*)d_in[0];
    const float* pls   = (const float*)d_in[3];
    const float* cos_s = (const float*)d_in[4];
    const float* sin_s = (const float*)d_in[5];
    const float* cos_f = (const float*)d_in[6];
    const float* sin_f = (const float*)d_in[7];
    const float* K_in  = (const float*)d_in[8];
    const float* V_in  = (const float*)d_in[9];
    const float* Wq    = (const float*)d_in[10];
    const float* Wk    = (const float*)d_in[11];
    const float* Wv    = (const float*)d_in[12];
    const float* Wo    = (const float*)d_in[13];
    const float* qn    = (const float*)d_in[14];
    const float* kn    = (const float*)d_in[15];
    const float* ln_in   = (const float*)d_in[16];
    const float* ln_pa   = (const float*)d_in[17];
    const float* ln_pre  = (const float*)d_in[18];
    const float* ln_post = (const float*)d_in[19];
    const float* ln_pl   = (const float*)d_in[20];
    const float* Wg    = (const float*)d_in[21];
    const float* Wu    = (const float*)d_in[22];
    const float* Wd    = (const float*)d_in[23];
    const float* Wplg  = (const float*)d_in[24];
    const float* Wplp  = (const float*)d_in[25];
    const float* lsc   = (const float*)d_in[26];

    float* out = (float*)d_out;
    const size_t kvsz = (size_t)NLAYER * NKV * SEQ * HDIM;  // 16,777,216
    float* outK = out + DMODEL;
    float* outV = outK + kvsz;

    float* sb = nullptr;
    cudaGetSymbolAddress((void**)&sb, g_scratch);
    float* b_h    = sb + OFF_H;
    float* b_hn   = sb + OFF_HN;
    float* b_q    = sb + OFF_Q;
    float* b_knew = sb + OFF_KNEW;
    float* b_vnew = sb + OFF_VNEW;
    float* b_attn = sb + OFF_ATTN;
    float* b_act  = sb + OFF_ACT;
    float* b_g2   = sb + OFF_G2;
    float* b_sc   = sb + OFF_SC;
    float* b_part = sb + OFF_PART;

    // bulk KV copy (old cache -> output); updated rows overwritten per-layer below
    k_copy_kv<<<1184, 256>>>((const float4*)K_in, (const float4*)V_in,
                             (float4*)outK, (float4*)outV, (int)(kvsz / 4));
    // h = hidden_states ; hn = rms(h)*ln_in[0]
    k_copy<<<8, 256>>>(hs, b_h, DMODEL);
    k_rms_scale<<<1, 512>>>(b_h, ln_in, b_hn);

    for (int l = 0; l < NLAYER; l++) {
        const float* Wq_l = Wq + (size_t)l * 2048 * 2048;
        const float* Wk_l = Wk + (size_t)l * 512 * 2048;
        const float* Wv_l = Wv + (size_t)l * 512 * 2048;
        const float* Wo_l = Wo + (size_t)l * 2048 * 2048;
        const float* Wg_l = Wg + (size_t)l * 8192 * 2048;
        const float* Wu_l = Wu + (size_t)l * 8192 * 2048;
        const float* Wd_l = Wd + (size_t)l * 2048 * 8192;
        const float* Wplg_l = Wplg + (size_t)l * 256 * 2048;
        const float* Wplp_l = Wplp + (size_t)l * 2048 * 256;
        const float* K_l = K_in + (size_t)l * NKV * SEQ * HDIM;
        const float* V_l = V_in + (size_t)l * NKV * SEQ * HDIM;
        float* outK_l = outK + (size_t)l * NKV * SEQ * HDIM;
        float* outV_l = outV + (size_t)l * NKV * SEQ * HDIM;
        bool full = ((l + 1) % 5) == 0;
        const float* cp = full ? cos_f : cos_s;
        const float* sp = full ? sin_f : sin_s;
        const float* ln_in_next = ln_in + ((l + 1 < NLAYER) ? (l + 1) : 0) * DMODEL;

        // attention block
        k_gemv_qkv_b8<<<768, 256>>>(Wq_l, Wk_l, Wv_l, b_hn, b_part);
        k_hnr<<<12, 256>>>(b_part, qn + l * HDIM, kn + l * HDIM, cp, sp,
                           b_q, b_knew, b_vnew, outK_l, outV_l);
        k_scores<<<dim3(8, 33), 256>>>(b_q, K_l, b_knew, b_sc);
        k_softmax<<<8, 256>>>(b_sc, b_attn);
        k_attnv<<<dim3(8, 33), 256>>>(b_sc, V_l, b_vnew, b_attn);
        k_gemv_b8<2048, 2048><<<512, 256>>>(Wo_l, b_attn, b_part);
        k_rms_add_norm<2><<<1, 512>>>(b_part, ln_pa + l * DMODEL, b_h,
                                      ln_pre + l * DMODEL, b_hn);
        // MLP block
        k_gemv_gateup<<<1024, 256>>>(Wg_l, Wu_l, b_hn, b_act);
        k_gemv_b8<2048, 8192><<<2048, 256>>>(Wd_l, b_act, b_part);
        k_rms_add<8><<<1, 512>>>(b_part, ln_post + l * DMODEL, b_h);
        // per-layer block
        k_plg_rowblock<<<256, 256>>>(Wplg_l, b_h, pls + l * PLDIM, b_g2);
        k_gemv<256><<<256, 256>>>(Wplp_l, b_g2, b_part);
        k_rms_add_scale_norm<<<1, 512>>>(b_part, ln_pl + l * DMODEL, lsc + l,
                                         b_h, ln_in_next, b_hn);
    }

    // final hidden state
    k_copy<<<8, 256>>>(b_h, out, DMODEL);
}